// round 15
// baseline (speedup 1.0000x reference)
#include <cuda_runtime.h>
#include <cuda_fp16.h>
#include <cstdint>

// VectorQuantizer via mma.sync.m16n8k16 fp16 single-term (HMMA on sm_103).
// Round 15: B stored as -2c (fp16, exact) + D initialized with biased cn
// => MMA emits scores directly (no FFMA epilogue). Pair-min packed keys
// (top-3 pairs/position), split exact fp32 re-rank of the 6 pair members.
// latents [64,64,32,32] f32, codebook [1024,64] f32 ->
// out[0..4194303] = codebook[argmin], out[4194304] = 1.25*mean((q-x)^2).

#define DIMS    64
#define KCODES  1024
#define HW      1024
#define THREADS 128
#define NPOS    65536
#define POSC    64
#define NBLOCKS (NPOS / POSC)             // 1024
#define PITCH   144                       // 128B fp16 row + 16B pad
#define TILE_CODES 128
#define TILE_BYTES (TILE_CODES * PITCH)   // 18432
#define NTILES  8
#define BIAS    16.0f                     // makes all scores positive

// smem layout
#define SM_A     0                        // 64 x 144 = 9216
#define SM_B0    9216
#define SM_B1    27648
#define SM_CN    46080                    // 1024 f32 (biased: cn + 16)
#define SM_I0    50176                    // 64 int (padded 512)
#define SM_I1    50688
#define SM_I2    51200
#define SM_RED   51712                    // 128 f32
#define SM_RS    52224                    // 128 f32 (split re-rank scores)
#define SM_RC    52736                    // 128 int  (split re-rank cols)
#define SM_TOTAL 53248

__device__ float g_cnorm[KCODES];         // biased: ||c||^2 + 16
__device__ float g_partial[NBLOCKS];
__device__ __align__(16) unsigned char g_cb[KCODES * PITCH];   // holds -2c fp16

__device__ __forceinline__ uint32_t smem_u32(const void* p) {
    uint32_t a;
    asm("{ .reg .u64 t; cvta.to.shared.u64 t, %1; cvt.u32.u64 %0, t; }"
        : "=r"(a) : "l"(p));
    return a;
}

__device__ __forceinline__ uint32_t pack_h2(float v0, float v1) {
    __half h0 = __float2half_rn(v0), h1 = __float2half_rn(v1);
    return (uint32_t)__half_as_ushort(h0) |
           ((uint32_t)__half_as_ushort(h1) << 16);
}

// positive-float ordered key: raw bits monotone; low 9 bits = pair index
__device__ __forceinline__ int pack_key(float s, int lidx) {
    return (__float_as_int(s) & ~511) | lidx;        // 1 LOP3
}
// lidx bits (monotone in pair base col): [8:6]=tb [5:3]=np [2]=j [1:0]=c
__device__ __forceinline__ int key_col(int k) {
    int l = k & 511;
    return ((l >> 6) & 7) * 128 + ((l >> 3) & 7) * 16
         + ((l >> 2) & 1) * 8 + (l & 3) * 2;         // pair base col
}

#define MMA(d, a, bb) \
    asm volatile("mma.sync.aligned.m16n8k16.row.col.f32.f16.f16.f32 " \
                 "{%0,%1,%2,%3}, {%4,%5,%6,%7}, {%8,%9}, {%0,%1,%2,%3};" \
                 : "+f"((d)[0]), "+f"((d)[1]), "+f"((d)[2]), "+f"((d)[3]) \
                 : "r"((a)[0]), "r"((a)[1]), "r"((a)[2]), "r"((a)[3]), \
                   "r"((bb)[0]), "r"((bb)[1]))

__device__ __forceinline__ void cpa16(uint32_t dst, const void* src) {
    asm volatile("cp.async.cg.shared.global [%0], [%1], 16;" :: "r"(dst), "l"(src));
}
#define CPA_COMMIT() asm volatile("cp.async.commit_group;" ::: "memory")
#define CPA_WAIT1()  asm volatile("cp.async.wait_group 1;" ::: "memory")

// branchless sorted top-3 insert on packed int keys (5x IMNMX)
#define INS3I(rr, kk) \
    do { int _k = (kk); \
         int _t0 = ::min(_k, kw[rr][0]); int _m0 = ::max(_k, kw[rr][0]); \
         int _t1 = ::min(_m0, kw[rr][1]); int _m1 = ::max(_m0, kw[rr][1]); \
         int _t2 = ::min(_m1, kw[rr][2]); \
         kw[rr][0] = _t0; kw[rr][1] = _t1; kw[rr][2] = _t2; } while (0)

// ---------------------------------------------------------------------------
// Prep: 8 threads/code -> fp16 (-2c) row image + BIASED fp32 ||c||^2 + 16
// ---------------------------------------------------------------------------
__global__ void prep_kernel(const float* __restrict__ cb) {
    const int idx = blockIdx.x * blockDim.x + threadIdx.x;   // 8192 threads
    const int k = idx >> 3;
    const int j = idx & 7;
    const float* row = cb + k * DIMS;
    unsigned char* dst = g_cb + (size_t)k * PITCH;
    float cn = 0.f;
    #pragma unroll
    for (int c = 0; c < 4; ++c) {
        const int d = 8 * j + 2 * c;
        float v0 = row[d], v1 = row[d + 1];
        cn = fmaf(v1, v1, fmaf(v0, v0, cn));
        // store -2c: exact in fp16 (exponent shift of rn(c))
        *(uint32_t*)(dst + c * 32 + j * 4) = pack_h2(-2.f * v0, -2.f * v1);
    }
    cn += __shfl_down_sync(0xffffffffu, cn, 4);
    cn += __shfl_down_sync(0xffffffffu, cn, 2);
    cn += __shfl_down_sync(0xffffffffu, cn, 1);
    if (j == 0) g_cnorm[k] = cn + BIAS;
}

// ---------------------------------------------------------------------------
// Main kernel
// ---------------------------------------------------------------------------
__global__ __launch_bounds__(THREADS, 4) void vq_mma_kernel(
    const float* __restrict__ latents,
    const float* __restrict__ cb,
    float* __restrict__ out)
{
    extern __shared__ unsigned char smem[];
    const uint32_t sb = smem_u32(smem);
    const int tid  = threadIdx.x;
    const int w    = tid >> 5;
    const int lane = tid & 31;
    const int g    = lane >> 2;
    const int c    = lane & 3;

    // prefetch B tiles 0 and 1
    #pragma unroll
    for (int i = 0; i < 9; ++i)
        cpa16(sb + SM_B0 + tid * 16 + i * 2048, g_cb + tid * 16 + i * 2048);
    CPA_COMMIT();
    #pragma unroll
    for (int i = 0; i < 9; ++i)
        cpa16(sb + SM_B1 + tid * 16 + i * 2048,
              g_cb + TILE_BYTES + tid * 16 + i * 2048);
    CPA_COMMIT();

    // biased cnorm -> smem
    #pragma unroll
    for (int i = tid; i < KCODES / 4; i += THREADS)
        ((float4*)(smem + SM_CN))[i] = ((const float4*)g_cnorm)[i];

    // ---- build A rows (tid < 64: one position each), fp16 c-grouped ----
    const int prow = tid & 63;
    const int p  = blockIdx.x * POSC + prow;
    const int b  = p >> 10;
    const int hw = p & (HW - 1);
    const float* xin = latents + (size_t)b * (DIMS * HW) + hw;
    float xnorm = 0.f;
    if (tid < POSC) {
        unsigned char* arow = smem + SM_A + tid * PITCH;
        float xn0 = 0.f, xn1 = 0.f;
        #pragma unroll
        for (int cc = 0; cc < 4; ++cc)
            #pragma unroll
            for (int ww = 0; ww < 8; ++ww) {
                const int d = 8 * ww + 2 * cc;
                float v0 = xin[d * HW], v1 = xin[(d + 1) * HW];
                xn0 = fmaf(v0, v0, xn0); xn1 = fmaf(v1, v1, xn1);
                *(uint32_t*)(arow + cc * 32 + ww * 4) = pack_h2(v0, v1);
            }
        xnorm = xn0 + xn1;
    }
    __syncthreads();

    // ---- load A fragments (resident): warp w owns rows 16w..16w+15 ----
    uint32_t aa[4][4];
    const int rbase = 16 * w + g;
    {
        const unsigned char* r0 = smem + SM_A + rbase * PITCH + c * 32;
        const unsigned char* r8 = r0 + 8 * PITCH;
        uint4 q0a = *(const uint4*)(r0);
        uint4 q0b = *(const uint4*)(r0 + 16);
        uint4 q8a = *(const uint4*)(r8);
        uint4 q8b = *(const uint4*)(r8 + 16);
        aa[0][0] = q0a.x; aa[0][1] = q8a.x; aa[0][2] = q0a.y; aa[0][3] = q8a.y;
        aa[1][0] = q0a.z; aa[1][1] = q8a.z; aa[1][2] = q0a.w; aa[1][3] = q8a.w;
        aa[2][0] = q0b.x; aa[2][1] = q8b.x; aa[2][2] = q0b.y; aa[2][3] = q8b.y;
        aa[3][0] = q0b.z; aa[3][1] = q8b.z; aa[3][2] = q0b.w; aa[3][3] = q8b.w;
    }

    // per-thread top-3 packed-key windows for the 2 rows (rbase, rbase+8)
    int kw[2][3] = {{0x7FFFFFFF, 0x7FFFFFFF, 0x7FFFFFFF},
                    {0x7FFFFFFF, 0x7FFFFFFF, 0x7FFFFFFF}};

    #pragma unroll 1
    for (int tb = 0; tb < NTILES; ++tb) {
        CPA_WAIT1();
        __syncthreads();
        const unsigned char* bbuf = smem + SM_B0 + (tb & 1) * TILE_BYTES;

        #pragma unroll 1
        for (int np = 0; np < 8; ++np) {
            uint32_t bb[2][4][2];
            #pragma unroll
            for (int j = 0; j < 2; ++j) {
                const unsigned char* rb =
                    bbuf + ((2 * np + j) * 8 + g) * PITCH + c * 32;
                uint4 q0 = *(const uint4*)(rb);
                uint4 q1 = *(const uint4*)(rb + 16);
                bb[j][0][0] = q0.x; bb[j][0][1] = q0.y;
                bb[j][1][0] = q0.z; bb[j][1][1] = q0.w;
                bb[j][2][0] = q1.x; bb[j][2][1] = q1.y;
                bb[j][3][0] = q1.z; bb[j][3][1] = q1.w;
            }

            // D initialized with biased cn: MMA (B = -2c) emits scores directly
            const int cb0 = tb * TILE_CODES + np * 16 + 2 * c;
            const float2 cnA = *(const float2*)(smem + SM_CN + cb0 * 4);
            const float2 cnB = *(const float2*)(smem + SM_CN + (cb0 + 8) * 4);
            float D[2][4];
            D[0][0] = cnA.x; D[0][1] = cnA.y; D[0][2] = cnA.x; D[0][3] = cnA.y;
            D[1][0] = cnB.x; D[1][1] = cnB.y; D[1][2] = cnB.x; D[1][3] = cnB.y;

            #pragma unroll
            for (int kt = 0; kt < 4; ++kt) {
                MMA(D[0], aa[kt], bb[0][kt]);
                MMA(D[1], aa[kt], bb[1][kt]);
            }

            // ---- pair-min packed-key epilogue ----
            const int lp = (tb << 6) | (np << 3) | c;   // j=0 pair lidx
            {   // row rbase
                float m0 = fminf(D[0][0], D[0][1]);
                float m1 = fminf(D[1][0], D[1][1]);
                INS3I(0, pack_key(m0, lp));
                INS3I(0, pack_key(m1, lp | 4));
            }
            {   // row rbase+8
                float m0 = fminf(D[0][2], D[0][3]);
                float m1 = fminf(D[1][2], D[1][3]);
                INS3I(1, pack_key(m0, lp));
                INS3I(1, pack_key(m1, lp | 4));
            }
        }

        __syncthreads();
        if (tb + 2 < NTILES) {
            const uint32_t bdst = sb + SM_B0 + (tb & 1) * TILE_BYTES;
            #pragma unroll
            for (int i = 0; i < 9; ++i)
                cpa16(bdst + tid * 16 + i * 2048,
                      g_cb + (size_t)(tb + 2) * TILE_BYTES + tid * 16 + i * 2048);
        }
        CPA_COMMIT();
    }

    // ---- merge top-3 keys across the 4 lanes (c) sharing each row ----
    #pragma unroll
    for (int m = 1; m <= 2; m <<= 1) {
        int ov[2][3];
        #pragma unroll
        for (int rr = 0; rr < 2; ++rr)
            #pragma unroll
            for (int t = 0; t < 3; ++t)
                ov[rr][t] = __shfl_xor_sync(0xffffffffu, kw[rr][t], m);
        #pragma unroll
        for (int rr = 0; rr < 2; ++rr)
            #pragma unroll
            for (int t = 0; t < 3; ++t)
                INS3I(rr, ov[rr][t]);
    }
    int* sI0 = (int*)(smem + SM_I0);
    int* sI1 = (int*)(smem + SM_I1);
    int* sI2 = (int*)(smem + SM_I2);
    if (c == 0) {
        sI0[rbase]     = key_col(kw[0][0]);
        sI1[rbase]     = key_col(kw[0][1]);
        sI2[rbase]     = key_col(kw[0][2]);
        sI0[rbase + 8] = key_col(kw[1][0]);
        sI1[rbase + 8] = key_col(kw[1][1]);
        sI2[rbase + 8] = key_col(kw[1][2]);
    }
    __syncthreads();

    // ---- split exact fp32 re-rank of the 6 pair members:
    //      lower half: {p0, p0+1, p1}; upper half: {p1+1, p2, p2+1}
    const float* cnS = (const float*)(smem + SM_CN);
    float* sRS = (float*)(smem + SM_RS);
    int*   sRC = (int*)(smem + SM_RC);
    {
        const int pa = sI0[prow], pbq = sI1[prow], pcq = sI2[prow];
        int c0, c1v, c2v;
        if (tid < 64) { c0 = pa;      c1v = pa + 1;  c2v = pbq; }
        else          { c0 = pbq + 1; c1v = pcq;     c2v = pcq + 1; }
        const float4* p0 = (const float4*)(cb + (size_t)c0  * DIMS);
        const float4* p1 = (const float4*)(cb + (size_t)c1v * DIMS);
        const float4* p2 = (const float4*)(cb + (size_t)c2v * DIMS);
        float a0 = 0.f, a1 = 0.f, a2 = 0.f, a3 = 0.f;
        float b0 = 0.f, b1 = 0.f, b2 = 0.f, b3 = 0.f;
        float e0 = 0.f, e1 = 0.f, e2 = 0.f, e3 = 0.f;
        #pragma unroll
        for (int d4 = 0; d4 < DIMS / 4; ++d4) {
            float x0 = xin[(4 * d4 + 0) * HW], x1 = xin[(4 * d4 + 1) * HW];
            float x2 = xin[(4 * d4 + 2) * HW], x3 = xin[(4 * d4 + 3) * HW];
            float4 v0 = p0[d4], v1 = p1[d4], v2 = p2[d4];
            a0 = fmaf(x0, v0.x, a0); a1 = fmaf(x1, v0.y, a1);
            a2 = fmaf(x2, v0.z, a2); a3 = fmaf(x3, v0.w, a3);
            b0 = fmaf(x0, v1.x, b0); b1 = fmaf(x1, v1.y, b1);
            b2 = fmaf(x2, v1.z, b2); b3 = fmaf(x3, v1.w, b3);
            e0 = fmaf(x0, v2.x, e0); e1 = fmaf(x1, v2.y, e1);
            e2 = fmaf(x2, v2.z, e2); e3 = fmaf(x3, v2.w, e3);
        }
        float s0 = fmaf(-2.f, (a0 + a1) + (a2 + a3), cnS[c0]);
        float s1 = fmaf(-2.f, (b0 + b1) + (b2 + b3), cnS[c1v]);
        float s2 = fmaf(-2.f, (e0 + e1) + (e2 + e3), cnS[c2v]);
        int   fi = c0;
        float ff = s0;
        if (s1 < ff || (s1 == ff && c1v < fi)) { fi = c1v; ff = s1; }
        if (s2 < ff || (s2 == ff && c2v < fi)) { fi = c2v; ff = s2; }
        sRS[tid] = ff;
        sRC[tid] = fi;
    }
    __syncthreads();

    // ---- combine halves, output, loss (tid < 64) ----
    float fs = 0.f;
    if (tid < POSC) {
        fs = sRS[tid];
        int fin = sRC[tid];
        float s2 = sRS[tid + 64];
        int   c2 = sRC[tid + 64];
        if (s2 < fs || (s2 == fs && c2 < fin)) { fs = s2; fin = c2; }

        const float4* cc = (const float4*)(cb + (size_t)fin * DIMS);
        float* o = out + (size_t)b * (DIMS * HW) + hw;
        #pragma unroll
        for (int i = 0; i < DIMS / 4; ++i) {
            float4 v = cc[i];
            o[(4 * i + 0) * HW] = v.x;
            o[(4 * i + 1) * HW] = v.y;
            o[(4 * i + 2) * HW] = v.z;
            o[(4 * i + 3) * HW] = v.w;
        }
        fs -= BIAS;   // un-bias for the loss
    }

    // ---- loss partial (deterministic block tree over 64 positions) ----
    float* red = (float*)(smem + SM_RED);
    red[tid] = (tid < POSC) ? (xnorm + fs) : 0.f;
    __syncthreads();
    #pragma unroll
    for (int s = THREADS / 2; s > 0; s >>= 1) {
        if (tid < s) red[tid] += red[tid + s];
        __syncthreads();
    }
    if (tid == 0) g_partial[blockIdx.x] = red[0];
}

// ---------------------------------------------------------------------------
__global__ void loss_kernel(float* __restrict__ out, int ndhw) {
    __shared__ float red[NBLOCKS];
    red[threadIdx.x] = g_partial[threadIdx.x];
    __syncthreads();
    #pragma unroll
    for (int s = NBLOCKS / 2; s > 0; s >>= 1) {
        if (threadIdx.x < s) red[threadIdx.x] += red[threadIdx.x + s];
        __syncthreads();
    }
    if (threadIdx.x == 0)
        out[ndhw] = 1.25f * red[0] / (float)ndhw;
}

// ---------------------------------------------------------------------------
extern "C" void kernel_launch(void* const* d_in, const int* in_sizes, int n_in,
                              void* d_out, int out_size) {
    const float* latents = (const float*)d_in[0];  // [64,64,32,32]
    const float* cb      = (const float*)d_in[1];  // [1024,64]
    float* out = (float*)d_out;
    const int ndhw = in_sizes[0];                  // 4194304

    static int smem_set = 0;
    if (!smem_set) {
        cudaFuncSetAttribute(vq_mma_kernel,
                             cudaFuncAttributeMaxDynamicSharedMemorySize, SM_TOTAL);
        smem_set = 1;
    }

    prep_kernel<<<64, 128>>>(cb);
    vq_mma_kernel<<<NBLOCKS, THREADS, SM_TOTAL>>>(latents, cb, out);
    loss_kernel<<<1, NBLOCKS>>>(out, ndhw);
}

// round 16
// speedup vs baseline: 1.2506x; 1.2506x over previous
#include <cuda_runtime.h>
#include <cuda_fp16.h>
#include <cstdint>

// VectorQuantizer via mma.sync.m16n8k16 fp16 single-term (HMMA on sm_103).
// Round 16: R14 (best: 65.7us) + 4-wide N-block inner loop: 16 MMAs per
// iteration in 4 independent accumulator chains (2x MMA ILP, half the loop
// iterations). Same per-position op counts as R14.
// latents [64,64,32,32] f32, codebook [1024,64] f32 ->
// out[0..4194303] = codebook[argmin], out[4194304] = 1.25*mean((q-x)^2).

#define DIMS    64
#define KCODES  1024
#define HW      1024
#define THREADS 128
#define NPOS    65536
#define POSC    64
#define NBLOCKS (NPOS / POSC)             // 1024
#define PITCH   144                       // 128B fp16 row + 16B pad
#define TILE_CODES 128
#define TILE_BYTES (TILE_CODES * PITCH)   // 18432
#define NTILES  8
#define BIAS    16.0f                     // makes all scores positive

// smem layout
#define SM_A     0                        // 64 x 144 = 9216
#define SM_B0    9216
#define SM_B1    27648
#define SM_CN    46080                    // 1024 f32 (biased: cn + 16)
#define SM_I0    50176                    // 64 int (padded 512)
#define SM_I1    50688
#define SM_I2    51200
#define SM_RED   51712                    // 128 f32
#define SM_RS    52224                    // 128 f32 (split re-rank scores)
#define SM_RC    52736                    // 128 int  (split re-rank cols)
#define SM_TOTAL 53248

__device__ float g_cnorm[KCODES];         // biased: ||c||^2 + 16
__device__ float g_partial[NBLOCKS];
__device__ __align__(16) unsigned char g_cb[KCODES * PITCH];

__device__ __forceinline__ uint32_t smem_u32(const void* p) {
    uint32_t a;
    asm("{ .reg .u64 t; cvta.to.shared.u64 t, %1; cvt.u32.u64 %0, t; }"
        : "=r"(a) : "l"(p));
    return a;
}

__device__ __forceinline__ uint32_t pack_h2(float v0, float v1) {
    __half h0 = __float2half_rn(v0), h1 = __float2half_rn(v1);
    return (uint32_t)__half_as_ushort(h0) |
           ((uint32_t)__half_as_ushort(h1) << 16);
}

// positive-float ordered key: raw bits monotone; low 10 bits = index
__device__ __forceinline__ int pack_key(float s, int lidx) {
    return (__float_as_int(s) & ~1023) | lidx;       // 1 LOP3
}
// lidx bits (monotone in column): [9:7]=tb [6:3]=ntile [2:1]=c [0]=e
__device__ __forceinline__ int key_col(int k) {
    int l = k & 1023;
    return ((l >> 7) & 7) * 128 + ((l >> 3) & 15) * 8
         + ((l >> 1) & 3) * 2 + (l & 1);
}

#define MMA(d, a, bb) \
    asm volatile("mma.sync.aligned.m16n8k16.row.col.f32.f16.f16.f32 " \
                 "{%0,%1,%2,%3}, {%4,%5,%6,%7}, {%8,%9}, {%0,%1,%2,%3};" \
                 : "+f"((d)[0]), "+f"((d)[1]), "+f"((d)[2]), "+f"((d)[3]) \
                 : "r"((a)[0]), "r"((a)[1]), "r"((a)[2]), "r"((a)[3]), \
                   "r"((bb)[0]), "r"((bb)[1]))

__device__ __forceinline__ void cpa16(uint32_t dst, const void* src) {
    asm volatile("cp.async.cg.shared.global [%0], [%1], 16;" :: "r"(dst), "l"(src));
}
#define CPA_COMMIT() asm volatile("cp.async.commit_group;" ::: "memory")
#define CPA_WAIT1()  asm volatile("cp.async.wait_group 1;" ::: "memory")

// branchless sorted top-3 insert on packed int keys (5x IMNMX)
#define INS3I(rr, kk) \
    do { int _k = (kk); \
         int _t0 = ::min(_k, kw[rr][0]); int _m0 = ::max(_k, kw[rr][0]); \
         int _t1 = ::min(_m0, kw[rr][1]); int _m1 = ::max(_m0, kw[rr][1]); \
         int _t2 = ::min(_m1, kw[rr][2]); \
         kw[rr][0] = _t0; kw[rr][1] = _t1; kw[rr][2] = _t2; } while (0)

// ---------------------------------------------------------------------------
// Prep: 8 threads/code -> fp16 row image (c-grouped) + BIASED fp32 ||c||^2+16
// ---------------------------------------------------------------------------
__global__ void prep_kernel(const float* __restrict__ cb) {
    const int idx = blockIdx.x * blockDim.x + threadIdx.x;   // 8192 threads
    const int k = idx >> 3;
    const int j = idx & 7;
    const float* row = cb + k * DIMS;
    unsigned char* dst = g_cb + (size_t)k * PITCH;
    float cn = 0.f;
    #pragma unroll
    for (int c = 0; c < 4; ++c) {
        const int d = 8 * j + 2 * c;
        float v0 = row[d], v1 = row[d + 1];
        cn = fmaf(v1, v1, fmaf(v0, v0, cn));
        *(uint32_t*)(dst + c * 32 + j * 4) = pack_h2(v0, v1);
    }
    cn += __shfl_down_sync(0xffffffffu, cn, 4);
    cn += __shfl_down_sync(0xffffffffu, cn, 2);
    cn += __shfl_down_sync(0xffffffffu, cn, 1);
    if (j == 0) g_cnorm[k] = cn + BIAS;
}

// ---------------------------------------------------------------------------
// Main kernel
// ---------------------------------------------------------------------------
__global__ __launch_bounds__(THREADS, 4) void vq_mma_kernel(
    const float* __restrict__ latents,
    const float* __restrict__ cb,
    float* __restrict__ out)
{
    extern __shared__ unsigned char smem[];
    const uint32_t sb = smem_u32(smem);
    const int tid  = threadIdx.x;
    const int w    = tid >> 5;
    const int lane = tid & 31;
    const int g    = lane >> 2;
    const int c    = lane & 3;

    // prefetch B tiles 0 and 1
    #pragma unroll
    for (int i = 0; i < 9; ++i)
        cpa16(sb + SM_B0 + tid * 16 + i * 2048, g_cb + tid * 16 + i * 2048);
    CPA_COMMIT();
    #pragma unroll
    for (int i = 0; i < 9; ++i)
        cpa16(sb + SM_B1 + tid * 16 + i * 2048,
              g_cb + TILE_BYTES + tid * 16 + i * 2048);
    CPA_COMMIT();

    // biased cnorm -> smem
    #pragma unroll
    for (int i = tid; i < KCODES / 4; i += THREADS)
        ((float4*)(smem + SM_CN))[i] = ((const float4*)g_cnorm)[i];

    // ---- build A rows (tid < 64: one position each), fp16 c-grouped ----
    const int prow = tid & 63;
    const int p  = blockIdx.x * POSC + prow;
    const int b  = p >> 10;
    const int hw = p & (HW - 1);
    const float* xin = latents + (size_t)b * (DIMS * HW) + hw;
    float xnorm = 0.f;
    if (tid < POSC) {
        unsigned char* arow = smem + SM_A + tid * PITCH;
        float xn0 = 0.f, xn1 = 0.f;
        #pragma unroll
        for (int cc = 0; cc < 4; ++cc)
            #pragma unroll
            for (int ww = 0; ww < 8; ++ww) {
                const int d = 8 * ww + 2 * cc;
                float v0 = xin[d * HW], v1 = xin[(d + 1) * HW];
                xn0 = fmaf(v0, v0, xn0); xn1 = fmaf(v1, v1, xn1);
                *(uint32_t*)(arow + cc * 32 + ww * 4) = pack_h2(v0, v1);
            }
        xnorm = xn0 + xn1;
    }
    __syncthreads();

    // ---- load A fragments (resident): warp w owns rows 16w..16w+15 ----
    uint32_t aa[4][4];
    const int rbase = 16 * w + g;
    {
        const unsigned char* r0 = smem + SM_A + rbase * PITCH + c * 32;
        const unsigned char* r8 = r0 + 8 * PITCH;
        uint4 q0a = *(const uint4*)(r0);
        uint4 q0b = *(const uint4*)(r0 + 16);
        uint4 q8a = *(const uint4*)(r8);
        uint4 q8b = *(const uint4*)(r8 + 16);
        aa[0][0] = q0a.x; aa[0][1] = q8a.x; aa[0][2] = q0a.y; aa[0][3] = q8a.y;
        aa[1][0] = q0a.z; aa[1][1] = q8a.z; aa[1][2] = q0a.w; aa[1][3] = q8a.w;
        aa[2][0] = q0b.x; aa[2][1] = q8b.x; aa[2][2] = q0b.y; aa[2][3] = q8b.y;
        aa[3][0] = q0b.z; aa[3][1] = q8b.z; aa[3][2] = q0b.w; aa[3][3] = q8b.w;
    }

    // per-thread top-3 packed-key windows for the 2 rows (rbase, rbase+8)
    int kw[2][3] = {{0x7FFFFFFF, 0x7FFFFFFF, 0x7FFFFFFF},
                    {0x7FFFFFFF, 0x7FFFFFFF, 0x7FFFFFFF}};

    #pragma unroll 1
    for (int tb = 0; tb < NTILES; ++tb) {
        CPA_WAIT1();
        __syncthreads();
        const unsigned char* bbuf = smem + SM_B0 + (tb & 1) * TILE_BYTES;

        #pragma unroll 1
        for (int np = 0; np < 4; ++np) {
            // B fragments for 4 n-tiles: 8x LDS.128
            uint32_t bb[4][4][2];
            #pragma unroll
            for (int j = 0; j < 4; ++j) {
                const unsigned char* rb =
                    bbuf + ((4 * np + j) * 8 + g) * PITCH + c * 32;
                uint4 q0 = *(const uint4*)(rb);
                uint4 q1 = *(const uint4*)(rb + 16);
                bb[j][0][0] = q0.x; bb[j][0][1] = q0.y;
                bb[j][1][0] = q0.z; bb[j][1][1] = q0.w;
                bb[j][2][0] = q1.x; bb[j][2][1] = q1.y;
                bb[j][3][0] = q1.z; bb[j][3][1] = q1.w;
            }
            float D[4][4];
            #pragma unroll
            for (int j = 0; j < 4; ++j)
                #pragma unroll
                for (int q = 0; q < 4; ++q) D[j][q] = 0.f;

            // 16 MMAs in 4 independent chains
            #pragma unroll
            for (int kt = 0; kt < 4; ++kt) {
                MMA(D[0], aa[kt], bb[0][kt]);
                MMA(D[1], aa[kt], bb[1][kt]);
                MMA(D[2], aa[kt], bb[2][kt]);
                MMA(D[3], aa[kt], bb[3][kt]);
            }

            // ---- packed-key epilogue: 16 scores ----
            #pragma unroll
            for (int j = 0; j < 4; ++j) {
                const int jj  = 4 * np + j;
                const int lb  = (tb << 7) | (jj << 3) | (c << 1);
                const int cb0 = tb * TILE_CODES + jj * 8 + 2 * c;
                const float2 cn2 = *(const float2*)(smem + SM_CN + cb0 * 4);
                INS3I(0, pack_key(fmaf(-2.f, D[j][0], cn2.x), lb | 0));
                INS3I(0, pack_key(fmaf(-2.f, D[j][1], cn2.y), lb | 1));
                INS3I(1, pack_key(fmaf(-2.f, D[j][2], cn2.x), lb | 0));
                INS3I(1, pack_key(fmaf(-2.f, D[j][3], cn2.y), lb | 1));
            }
        }

        __syncthreads();
        if (tb + 2 < NTILES) {
            const uint32_t bdst = sb + SM_B0 + (tb & 1) * TILE_BYTES;
            #pragma unroll
            for (int i = 0; i < 9; ++i)
                cpa16(bdst + tid * 16 + i * 2048,
                      g_cb + (size_t)(tb + 2) * TILE_BYTES + tid * 16 + i * 2048);
        }
        CPA_COMMIT();
    }

    // ---- merge top-3 keys across the 4 lanes (c) sharing each row ----
    #pragma unroll
    for (int m = 1; m <= 2; m <<= 1) {
        int ov[2][3];
        #pragma unroll
        for (int rr = 0; rr < 2; ++rr)
            #pragma unroll
            for (int t = 0; t < 3; ++t)
                ov[rr][t] = __shfl_xor_sync(0xffffffffu, kw[rr][t], m);
        #pragma unroll
        for (int rr = 0; rr < 2; ++rr)
            #pragma unroll
            for (int t = 0; t < 3; ++t)
                INS3I(rr, ov[rr][t]);
    }
    int* sI0 = (int*)(smem + SM_I0);
    int* sI1 = (int*)(smem + SM_I1);
    int* sI2 = (int*)(smem + SM_I2);
    if (c == 0) {
        sI0[rbase]     = key_col(kw[0][0]);
        sI1[rbase]     = key_col(kw[0][1]);
        sI2[rbase]     = key_col(kw[0][2]);
        sI0[rbase + 8] = key_col(kw[1][0]);
        sI1[rbase + 8] = key_col(kw[1][1]);
        sI2[rbase + 8] = key_col(kw[1][2]);
    }
    __syncthreads();

    // ---- split exact fp32 re-rank (biased scores; bias cancels in compare):
    //      warps 0-1 -> cand0, warps 2-3 -> cand1,2
    const float* cnS = (const float*)(smem + SM_CN);
    float* sRS = (float*)(smem + SM_RS);
    int*   sRC = (int*)(smem + SM_RC);
    if (tid < 64) {
        const int ca = sI0[prow];
        const float4* pa = (const float4*)(cb + (size_t)ca * DIMS);
        float a0 = 0.f, a1 = 0.f, a2 = 0.f, a3 = 0.f;
        #pragma unroll
        for (int d4 = 0; d4 < DIMS / 4; ++d4) {
            float x0 = xin[(4 * d4 + 0) * HW], x1 = xin[(4 * d4 + 1) * HW];
            float x2 = xin[(4 * d4 + 2) * HW], x3 = xin[(4 * d4 + 3) * HW];
            float4 va = pa[d4];
            a0 = fmaf(x0, va.x, a0); a1 = fmaf(x1, va.y, a1);
            a2 = fmaf(x2, va.z, a2); a3 = fmaf(x3, va.w, a3);
        }
        sRS[tid] = fmaf(-2.f, (a0 + a1) + (a2 + a3), cnS[ca]);
        sRC[tid] = ca;
    } else {
        const int ca = sI1[prow];
        const int cc2 = sI2[prow];
        const float4* pa = (const float4*)(cb + (size_t)ca * DIMS);
        const float4* pc = (const float4*)(cb + (size_t)cc2 * DIMS);
        float a0 = 0.f, a1 = 0.f, a2 = 0.f, a3 = 0.f;
        float b0 = 0.f, b1 = 0.f, b2 = 0.f, b3 = 0.f;
        #pragma unroll
        for (int d4 = 0; d4 < DIMS / 4; ++d4) {
            float x0 = xin[(4 * d4 + 0) * HW], x1 = xin[(4 * d4 + 1) * HW];
            float x2 = xin[(4 * d4 + 2) * HW], x3 = xin[(4 * d4 + 3) * HW];
            float4 va = pa[d4], vc = pc[d4];
            a0 = fmaf(x0, va.x, a0); a1 = fmaf(x1, va.y, a1);
            a2 = fmaf(x2, va.z, a2); a3 = fmaf(x3, va.w, a3);
            b0 = fmaf(x0, vc.x, b0); b1 = fmaf(x1, vc.y, b1);
            b2 = fmaf(x2, vc.z, b2); b3 = fmaf(x3, vc.w, b3);
        }
        float sA = fmaf(-2.f, (a0 + a1) + (a2 + a3), cnS[ca]);
        float sB = fmaf(-2.f, (b0 + b1) + (b2 + b3), cnS[cc2]);
        int   fi = ca;
        float ff = sA;
        if (sB < ff || (sB == ff && cc2 < fi)) { fi = cc2; ff = sB; }
        sRS[tid] = ff;
        sRC[tid] = fi;
    }
    __syncthreads();

    // ---- combine halves, output, loss (tid < 64) ----
    float fs = 0.f;
    if (tid < POSC) {
        fs = sRS[tid];
        int fin = sRC[tid];
        float s2 = sRS[tid + 64];
        int   c2 = sRC[tid + 64];
        if (s2 < fs || (s2 == fs && c2 < fin)) { fs = s2; fin = c2; }

        const float4* cc = (const float4*)(cb + (size_t)fin * DIMS);
        float* o = out + (size_t)b * (DIMS * HW) + hw;
        #pragma unroll
        for (int i = 0; i < DIMS / 4; ++i) {
            float4 v = cc[i];
            o[(4 * i + 0) * HW] = v.x;
            o[(4 * i + 1) * HW] = v.y;
            o[(4 * i + 2) * HW] = v.z;
            o[(4 * i + 3) * HW] = v.w;
        }
        fs -= BIAS;   // un-bias for the loss
    }

    // ---- loss partial (deterministic block tree over 64 positions) ----
    float* red = (float*)(smem + SM_RED);
    red[tid] = (tid < POSC) ? (xnorm + fs) : 0.f;
    __syncthreads();
    #pragma unroll
    for (int s = THREADS / 2; s > 0; s >>= 1) {
        if (tid < s) red[tid] += red[tid + s];
        __syncthreads();
    }
    if (tid == 0) g_partial[blockIdx.x] = red[0];
}

// ---------------------------------------------------------------------------
__global__ void loss_kernel(float* __restrict__ out, int ndhw) {
    __shared__ float red[NBLOCKS];
    red[threadIdx.x] = g_partial[threadIdx.x];
    __syncthreads();
    #pragma unroll
    for (int s = NBLOCKS / 2; s > 0; s >>= 1) {
        if (threadIdx.x < s) red[threadIdx.x] += red[threadIdx.x + s];
        __syncthreads();
    }
    if (threadIdx.x == 0)
        out[ndhw] = 1.25f * red[0] / (float)ndhw;
}

// ---------------------------------------------------------------------------
extern "C" void kernel_launch(void* const* d_in, const int* in_sizes, int n_in,
                              void* d_out, int out_size) {
    const float* latents = (const float*)d_in[0];  // [64,64,32,32]
    const float* cb      = (const float*)d_in[1];  // [1024,64]
    float* out = (float*)d_out;
    const int ndhw = in_sizes[0];                  // 4194304

    static int smem_set = 0;
    if (!smem_set) {
        cudaFuncSetAttribute(vq_mma_kernel,
                             cudaFuncAttributeMaxDynamicSharedMemorySize, SM_TOTAL);
        smem_set = 1;
    }

    prep_kernel<<<64, 128>>>(cb);
    vq_mma_kernel<<<NBLOCKS, THREADS, SM_TOTAL>>>(latents, cb, out);
    loss_kernel<<<1, NBLOCKS>>>(out, ndhw);
}